// round 16
// baseline (speedup 1.0000x reference)
#include <cuda_runtime.h>
#include <cuda_bf16.h>
#include <cuda_fp16.h>
#include <cstdint>

#define N_MAX   100000
#define E_MAX   1600000
#define HID     64
#define IN_DIM  128

// ---------------- scratch (device globals; no allocation allowed) ----------
__device__ uint32_t g_h2[N_MAX * 32];    // MLP output features, half2-packed (128B/row)
__device__ float g_rnorm[N_MAX];         // 1 / max(||h||, 1e-12)
__device__ int   g_src[E_MAX];
__device__ int   g_dst[E_MAX];
__device__ int   g_rank[E_MAX];
__device__ int   g_deg[N_MAX];           // re-zeroed in scan3 for replay
__device__ int   g_incl[N_MAX];
__device__ int   g_rs[N_MAX];
__device__ int   g_re[N_MAX];
__device__ int   g_csr[E_MAX];
__device__ int   g_bsum[256];
__device__ int   g_boff[256];

typedef unsigned long long ull;

// ---------------- f32x2 packed helpers (Blackwell sm_100 PTX) --------------
__device__ __forceinline__ void ffma2(ull& d, ull a, ull b) {
    asm("fma.rn.f32x2 %0, %1, %2, %0;" : "+l"(d) : "l"(a), "l"(b));
}
__device__ __forceinline__ ull pack2(float x, float y) {
    ull r; asm("mov.b64 %0, {%1, %2};" : "=l"(r) : "f"(x), "f"(y)); return r;
}
__device__ __forceinline__ void unpack2(ull v, float& x, float& y) {
    asm("mov.b64 {%0, %1}, %2;" : "=f"(x), "=f"(y) : "l"(v));
}
// half2 (as u32) -> packed float2 (as ull)
__device__ __forceinline__ ull h2f2(uint32_t h) {
    float2 f = __half22float2(*(__half2*)&h);
    return pack2(f.x, f.y);
}

// ================= CSR side-stream kernel A: convert + count ===============
__global__ void k_convcount(const void* ei, int E, int N) {
    __shared__ int s_is64;
    int tid = threadIdx.x;
    if (tid < 32) {
        const long long* p = (const long long*)ei;
        bool bad = false;
        for (int k = tid; k < 64 && k < E; k += 32) {
            long long v = p[k];
            if (v < 0 || v >= (long long)N) bad = true;
        }
        unsigned m = __ballot_sync(0xffffffffu, bad);
        if (tid == 0) s_is64 = (m == 0);
    }
    __syncthreads();
    int e = (blockIdx.x * blockDim.x + tid) * 2;
    if (e >= E) return;
    int s0, d0, s1, d1;
    bool two = (e + 1) < E;
    if (s_is64) {
        const longlong2* p2 = (const longlong2*)ei;            // 16B aligned
        longlong2 sv = p2[e >> 1];
        longlong2 dv = p2[(E + e) >> 1];                       // E even
        s0 = (int)sv.x; s1 = (int)sv.y;
        d0 = (int)dv.x; d1 = (int)dv.y;
    } else {
        const int2* p2 = (const int2*)ei;
        int2 sv = p2[e >> 1];
        int2 dv = p2[(E + e) >> 1];
        s0 = sv.x; s1 = sv.y;
        d0 = dv.x; d1 = dv.y;
    }
    ((int2*)g_src)[e >> 1] = make_int2(s0, s1);
    ((int2*)g_dst)[e >> 1] = make_int2(d0, d1);
    int r0 = atomicAdd(&g_deg[d0], 1);
    int r1 = two ? atomicAdd(&g_deg[d1], 1) : 0;
    ((int2*)g_rank)[e >> 1] = make_int2(r0, r1);
}

// ================= CSR kernels B-D: 3-phase scan (no grid barrier) =========
__global__ void __launch_bounds__(1024) k_scan1(int N) {
    __shared__ int wsum[32];
    int t = threadIdx.x;
    int i = blockIdx.x * 1024 + t;
    int lane = t & 31, wid = t >> 5;
    int v = (i < N) ? g_deg[i] : 0;
    int sc = v;
#pragma unroll
    for (int o = 1; o < 32; o <<= 1) {
        int u = __shfl_up_sync(0xffffffffu, sc, o);
        if (lane >= o) sc += u;
    }
    if (lane == 31) wsum[wid] = sc;
    __syncthreads();
    if (wid == 0) {
        int wv = wsum[lane];
        int ws = wv;
#pragma unroll
        for (int o = 1; o < 32; o <<= 1) {
            int u = __shfl_up_sync(0xffffffffu, ws, o);
            if (lane >= o) ws += u;
        }
        wsum[lane] = ws - wv;   // exclusive warp offsets
    }
    __syncthreads();
    if (i < N) g_incl[i] = sc + wsum[wid];
    if (t == 1023) g_bsum[blockIdx.x] = sc + wsum[wid];
}

__global__ void k_scan2(int nblk) {
    __shared__ int wsum[32];
    int t = threadIdx.x;
    int lane = t & 31, wid = t >> 5;
    int v = (t < nblk) ? g_bsum[t] : 0;
    int sc = v;
#pragma unroll
    for (int o = 1; o < 32; o <<= 1) {
        int u = __shfl_up_sync(0xffffffffu, sc, o);
        if (lane >= o) sc += u;
    }
    if (lane == 31) wsum[wid] = sc;
    __syncthreads();
    if (wid == 0) {
        int wv = wsum[lane];
        int ws = wv;
#pragma unroll
        for (int o = 1; o < 32; o <<= 1) {
            int u = __shfl_up_sync(0xffffffffu, ws, o);
            if (lane >= o) ws += u;
        }
        wsum[lane] = ws - wv;
    }
    __syncthreads();
    if (t < 256) g_boff[t] = sc + wsum[wid] - v;   // exclusive
}

__global__ void k_scan3(int N) {
    int i = blockIdx.x * blockDim.x + threadIdx.x;
    if (i >= N) return;
    int v = g_deg[i];
    int tot = g_incl[i] + g_boff[i >> 10];
    g_rs[i] = tot - v;
    g_re[i] = tot;
    g_deg[i] = 0;                      // restore for next replay
}

// ================= CSR kernel E: scatter (atomic-free) =====================
__global__ void k_scatter(int E) {
    int e = blockIdx.x * blockDim.x + threadIdx.x;
    if (e >= E) return;
    int pos = g_rs[g_dst[e]] + g_rank[e];
    g_csr[pos] = g_src[e];
}

// ================= main-stream kernel: MLP (f32x2, 4 CTAs/SM) ==============
#define WREG_OFF  0            // 32768 B
#define STG_OFF   16384        // stage: 64 x 64 floats = 16384 (upper WREG half)
#define BIAS_OFF  32768        // 512 B
#define XT_OFF    33280        // xs_t/ht_t: 64 x 68 floats = 17408 -> ends 50688
#define HT_OFF    33280
#define SMEM_SZ   50688        // 4 CTAs/SM

__global__ void __launch_bounds__(256, 4) k_mlp(
    const float* __restrict__ x, const float* __restrict__ b1,
    const float* __restrict__ b2, const float* __restrict__ W1,
    const float* __restrict__ W2, int N)
{
    extern __shared__ char sm[];
    float2* Wreg = (float2*)(sm + WREG_OFF);
    float* stage = (float*)(sm + STG_OFF);
    float* bias = (float*)(sm + BIAS_OFF);
    float* xs_t = (float*)(sm + XT_OFF);
    float* ht_t = (float*)(sm + HT_OFF);

    int tid = threadIdx.x;
    int wid = tid >> 5, lane = tid & 31;
    int node0 = blockIdx.x * 64;
    int w8 = wid * 8;

    // W1 interleaved: Wreg[i*32+l] = (W1[i][l], W1[i][l+32]), i in [0,128)
    for (int idx = tid; idx < 128 * 32; idx += 256) {
        int i = idx >> 5, l = idx & 31;
        Wreg[idx] = make_float2(W1[i * 64 + l], W1[i * 64 + l + 32]);
    }
    if (tid < 64) { bias[tid] = b1[tid]; bias[64 + tid] = b2[tid]; }

    // ---- GEMM1, k-split into two 64-wide chunks (xs_t holds one chunk) ----
    ull acc0[4], acc1[4];
#pragma unroll
    for (int p = 0; p < 4; p++) { acc0[p] = 0ull; acc1[p] = 0ull; }

#pragma unroll
    for (int half = 0; half < 2; half++) {
        for (int idx = tid; idx < 64 * 64; idx += 256) {
            int n = idx >> 6, i = idx & 63;
            int node = node0 + n;
            float v = (node < N) ? x[(size_t)node * 128 + half * 64 + i] : 0.f;
            xs_t[i * 68 + n] = v;
        }
        __syncthreads();
#pragma unroll 2
        for (int i = 0; i < 64; i++) {
            float2 w = Wreg[(half * 64 + i) * 32 + lane];
            ull wp0 = pack2(w.x, w.x);
            ull wp1 = pack2(w.y, w.y);
            ulonglong2 a01 = *(const ulonglong2*)(xs_t + i * 68 + w8);
            ulonglong2 a23 = *(const ulonglong2*)(xs_t + i * 68 + w8 + 4);
            ffma2(acc0[0], a01.x, wp0); ffma2(acc1[0], a01.x, wp1);
            ffma2(acc0[1], a01.y, wp0); ffma2(acc1[1], a01.y, wp1);
            ffma2(acc0[2], a23.x, wp0); ffma2(acc1[2], a23.x, wp1);
            ffma2(acc0[3], a23.y, wp0); ffma2(acc1[3], a23.y, wp1);
        }
        __syncthreads();   // all warps done with this xs_t chunk
    }

    // load W2 interleaved into the (dead) W1 region lower half
    for (int idx = tid; idx < 64 * 32; idx += 256) {
        int i = idx >> 5, l = idx & 31;
        Wreg[idx] = make_float2(W2[i * 64 + l], W2[i * 64 + l + 32]);
    }

    // epilogue1: relu(+b1) -> ht_t[c*68 + n] (overlays dead xs_t)
    {
        float bA = bias[lane], bB = bias[lane + 32];
#pragma unroll
        for (int p = 0; p < 4; p++) {
            float hx, hy;
            unpack2(acc0[p], hx, hy);
            ht_t[lane * 68 + w8 + 2 * p]     = fmaxf(hx + bA, 0.f);
            ht_t[lane * 68 + w8 + 2 * p + 1] = fmaxf(hy + bA, 0.f);
            unpack2(acc1[p], hx, hy);
            ht_t[(lane + 32) * 68 + w8 + 2 * p]     = fmaxf(hx + bB, 0.f);
            ht_t[(lane + 32) * 68 + w8 + 2 * p + 1] = fmaxf(hy + bB, 0.f);
        }
    }
    __syncthreads();

    // ---- GEMM2 ----
#pragma unroll
    for (int p = 0; p < 4; p++) { acc0[p] = 0ull; acc1[p] = 0ull; }
#pragma unroll 2
    for (int i = 0; i < 64; i++) {
        float2 w = Wreg[i * 32 + lane];
        ull wp0 = pack2(w.x, w.x);
        ull wp1 = pack2(w.y, w.y);
        ulonglong2 a01 = *(const ulonglong2*)(ht_t + i * 68 + w8);
        ulonglong2 a23 = *(const ulonglong2*)(ht_t + i * 68 + w8 + 4);
        ffma2(acc0[0], a01.x, wp0); ffma2(acc1[0], a01.x, wp1);
        ffma2(acc0[1], a01.y, wp0); ffma2(acc1[1], a01.y, wp1);
        ffma2(acc0[2], a23.x, wp0); ffma2(acc1[2], a23.x, wp1);
        ffma2(acc0[3], a23.y, wp0); ffma2(acc1[3], a23.y, wp1);
    }

    // epilogue2: +b2 -> stage[n*64 + c] (upper WREG half; disjoint regions)
    {
        float bA = bias[64 + lane], bB = bias[64 + lane + 32];
#pragma unroll
        for (int p = 0; p < 4; p++) {
            float hx, hy;
            unpack2(acc0[p], hx, hy);
            stage[(w8 + 2 * p) * 64 + lane]     = hx + bA;
            stage[(w8 + 2 * p + 1) * 64 + lane] = hy + bA;
            unpack2(acc1[p], hx, hy);
            stage[(w8 + 2 * p) * 64 + lane + 32]     = hx + bB;
            stage[(w8 + 2 * p + 1) * 64 + lane + 32] = hy + bB;
        }
    }
    __syncthreads();

    // norms (fp32) + half2-packed global store (128B/row)
    {
        const float2* st2 = (const float2*)stage;
#pragma unroll
        for (int r = 0; r < 8; r++) {
            int n = w8 + r;
            int node = node0 + n;
            float2 v = st2[n * 32 + lane];
            float ss = v.x * v.x + v.y * v.y;
#pragma unroll
            for (int o = 16; o; o >>= 1) ss += __shfl_xor_sync(0xffffffffu, ss, o);
            if (node < N) {
                __half2 hv = __floats2half2_rn(v.x, v.y);
                g_h2[(size_t)node * 32 + lane] = *(uint32_t*)&hv;
                if (lane == 0) g_rnorm[node] = 1.f / fmaxf(sqrtf(ss), 1e-12f);
            }
        }
    }
}

// ================= final kernel: gather (octet-per-edge, fp16 rows) ========
// warp per dst; octet (8 lanes) per edge -> 4 edges in flight per warp.
// fp16 h rows are 128B: lane p8 loads uint4 = features 8p8..8p8+7 -> ONE
// full-line LDG.128 per edge (was 2 with fp32). All math stays fp32.
__global__ void __launch_bounds__(256, 4) k_gather(
    const float* __restrict__ beta_p, const float* __restrict__ Wc,
    const float* __restrict__ bc, float* __restrict__ out, int N)
{
    int wid = threadIdx.x >> 5;
    int lane = threadIdx.x & 31;
    int p8 = lane & 7, oc = lane >> 3;
    int n = blockIdx.x * 8 + wid;
    if (n >= N) return;

    float beta = __ldg(beta_p);
    float C = fabsf(beta);                 // |e| <= |beta| -> fixed softmax shift
    const uint4* h4 = (const uint4*)g_h2;  // 16B granules, 8 per row

    uint4 hdr = h4[(size_t)n * 8 + p8];
    ull hd[4];
    hd[0] = h2f2(hdr.x); hd[1] = h2f2(hdr.y);
    hd[2] = h2f2(hdr.z); hd[3] = h2f2(hdr.w);
    float rnd = __ldg(&g_rnorm[n]);

    // self-dot: octet covers all 64 features
    ull d2 = 0ull;
#pragma unroll
    for (int k = 0; k < 4; k++) ffma2(d2, hd[k], hd[k]);
    float dsx, dsy; unpack2(d2, dsx, dsy);
    float ds = dsx + dsy;
    ds += __shfl_xor_sync(0xffffffffu, ds, 1);
    ds += __shfl_xor_sync(0xffffffffu, ds, 2);
    ds += __shfl_xor_sync(0xffffffffu, ds, 4);
    float w_self = __expf(fmaf(beta * rnd * rnd, ds, -C));

    // acc in octet layout; self contribution counted once (octet 0 only)
    float wq = (oc == 0) ? w_self : 0.f;
    ull wqp = pack2(wq, wq);
    ull acc[4];
#pragma unroll
    for (int k = 0; k < 4; k++) { acc[k] = 0ull; ffma2(acc[k], wqp, hd[k]); }
    float s_lane = 0.f;

    int start = g_rs[n], end = g_re[n];
    float brnd = beta * rnd;
    for (int e0 = start; e0 < end; e0 += 4) {
        int eidx = e0 + oc;
        bool valid = eidx < end;
        int sidx = __ldg(&g_csr[valid ? eidx : e0]);
        float rns = __ldg(&g_rnorm[sidx]);
        uint4 hsr = h4[(size_t)sidx * 8 + p8];
        ull hs[4];
        hs[0] = h2f2(hsr.x); hs[1] = h2f2(hsr.y);
        hs[2] = h2f2(hsr.z); hs[3] = h2f2(hsr.w);

        ull dd = 0ull;
#pragma unroll
        for (int k = 0; k < 4; k++) ffma2(dd, hs[k], hd[k]);
        float dx, dy; unpack2(dd, dx, dy);
        float d = dx + dy;
        d += __shfl_xor_sync(0xffffffffu, d, 1);
        d += __shfl_xor_sync(0xffffffffu, d, 2);
        d += __shfl_xor_sync(0xffffffffu, d, 4);

        float w = __expf(fmaf(brnd * rns, d, -C));
        w = valid ? w : 0.f;
        s_lane += w;
        ull wp = pack2(w, w);
#pragma unroll
        for (int k = 0; k < 4; k++) ffma2(acc[k], wp, hs[k]);
    }

    // s: each edge's w was added in all 8 lanes of its octet -> /8 (exact)
#pragma unroll
    for (int o = 16; o; o >>= 1) s_lane += __shfl_xor_sync(0xffffffffu, s_lane, o);
    float s = fmaf(s_lane, 0.125f, w_self);
    float inv = 1.f / (s + 1e-16f);

    // classifier; warp-reduce sums over features AND octets simultaneously
    const float2* wc2 = (const float2*)Wc;   // wc2[f] = (Wc[f][0], Wc[f][1])
    float y0 = 0.f, y1 = 0.f;
#pragma unroll
    for (int k = 0; k < 4; k++) {
        int f0 = 8 * p8 + 2 * k;             // acc[k] holds features f0, f0+1
        float a0, a1;
        unpack2(acc[k], a0, a1);
        float2 w0 = wc2[f0], w1 = wc2[f0 + 1];
        y0 += a0 * w0.x + a1 * w1.x;
        y1 += a0 * w0.y + a1 * w1.y;
    }
#pragma unroll
    for (int o = 16; o; o >>= 1) {
        y0 += __shfl_xor_sync(0xffffffffu, y0, o);
        y1 += __shfl_xor_sync(0xffffffffu, y1, o);
    }
    if (lane == 0) {
        out[(size_t)n * 2]     = fmaf(y0, inv, __ldg(&bc[0]));
        out[(size_t)n * 2 + 1] = fmaf(y1, inv, __ldg(&bc[1]));
    }
}

// ---------------- launch: forked-stream graph ------------------------------
extern "C" void kernel_launch(void* const* d_in, const int* in_sizes, int n_in,
                              void* d_out, int out_size)
{
    const float* x    = (const float*)d_in[0];
    const void*  ei   = d_in[1];
    const float* W1   = (const float*)d_in[2];
    const float* b1   = (const float*)d_in[3];
    const float* W2   = (const float*)d_in[4];
    const float* b2   = (const float*)d_in[5];
    const float* beta = (const float*)d_in[6];
    const float* Wc   = (const float*)d_in[7];
    const float* bc   = (const float*)d_in[8];
    float* y = (float*)d_out;

    int hid    = in_sizes[3];            // 64
    int in_dim = in_sizes[2] / hid;      // 128
    int N      = in_sizes[0] / in_dim;   // 100000
    int E      = in_sizes[1] / 2;        // 1600000

    static cudaStream_t s2 = nullptr;
    static cudaEvent_t evFork = nullptr, evJoin = nullptr;
    if (s2 == nullptr) {
        cudaStreamCreateWithFlags(&s2, cudaStreamNonBlocking);
        cudaEventCreateWithFlags(&evFork, cudaEventDisableTiming);
        cudaEventCreateWithFlags(&evJoin, cudaEventDisableTiming);
        cudaFuncSetAttribute(k_mlp, cudaFuncAttributeMaxDynamicSharedMemorySize, SMEM_SZ);
    }

    int nblk = (N + 1023) / 1024;        // 98 blocks

    // fork: side stream begins after everything previously on main stream
    cudaEventRecord(evFork, 0);
    cudaStreamWaitEvent(s2, evFork, 0);

    k_convcount<<<(E / 2 + 255) / 256, 256, 0, s2>>>(ei, E, N);     // 1 (s2)
    k_scan1<<<nblk, 1024, 0, s2>>>(N);                              // 2 (s2)
    k_scan2<<<1, 256, 0, s2>>>(nblk);                               // 3 (s2)
    k_mlp<<<(N + 63) / 64, 256, SMEM_SZ>>>(x, b1, b2, W1, W2, N);   // 4 (main, profiled)
    k_scan3<<<(N + 255) / 256, 256, 0, s2>>>(N);                    // 5 (s2)
    k_scatter<<<(E + 255) / 256, 256, 0, s2>>>(E);                  // 6 (s2)

    // join: gather needs both the CSR (s2) and h/rnorm (main)
    cudaEventRecord(evJoin, s2);
    cudaStreamWaitEvent(0, evJoin, 0);
    k_gather<<<(N + 7) / 8, 256>>>(beta, Wc, bc, y, N);             // 7 (main)
}

// round 17
// speedup vs baseline: 1.0441x; 1.0441x over previous
#include <cuda_runtime.h>
#include <cuda_bf16.h>
#include <cstdint>

#define N_MAX   100000
#define E_MAX   1600000
#define HID     64
#define IN_DIM  128

// ---------------- scratch (device globals; no allocation allowed) ----------
__device__ float g_h[N_MAX * HID];       // MLP output features (fp32, 256B/row)
__device__ float g_rnorm[N_MAX];         // 1 / max(||h||, 1e-12)
__device__ int   g_src[E_MAX];
__device__ int   g_dst[E_MAX];
__device__ int   g_rank[E_MAX];
__device__ int   g_deg[N_MAX];           // re-zeroed in scan3 for replay
__device__ int   g_incl[N_MAX];
__device__ int   g_rs[N_MAX];
__device__ int   g_re[N_MAX];
__device__ int   g_csr[E_MAX];
__device__ int   g_bsum[256];
__device__ int   g_boff[256];

typedef unsigned long long ull;

// ---------------- f32x2 packed helpers (Blackwell sm_100 PTX) --------------
__device__ __forceinline__ void ffma2(ull& d, ull a, ull b) {
    asm("fma.rn.f32x2 %0, %1, %2, %0;" : "+l"(d) : "l"(a), "l"(b));
}
__device__ __forceinline__ ull pack2(float x, float y) {
    ull r; asm("mov.b64 %0, {%1, %2};" : "=l"(r) : "f"(x), "f"(y)); return r;
}
__device__ __forceinline__ void unpack2(ull v, float& x, float& y) {
    asm("mov.b64 {%0, %1}, %2;" : "=f"(x), "=f"(y) : "l"(v));
}

// ================= CSR side-stream kernel A: convert + count ===============
__global__ void k_convcount(const void* ei, int E, int N) {
    __shared__ int s_is64;
    int tid = threadIdx.x;
    if (tid < 32) {
        const long long* p = (const long long*)ei;
        bool bad = false;
        for (int k = tid; k < 64 && k < E; k += 32) {
            long long v = p[k];
            if (v < 0 || v >= (long long)N) bad = true;
        }
        unsigned m = __ballot_sync(0xffffffffu, bad);
        if (tid == 0) s_is64 = (m == 0);
    }
    __syncthreads();
    int e = (blockIdx.x * blockDim.x + tid) * 2;
    if (e >= E) return;
    int s0, d0, s1, d1;
    bool two = (e + 1) < E;
    if (s_is64) {
        const longlong2* p2 = (const longlong2*)ei;            // 16B aligned
        longlong2 sv = p2[e >> 1];
        longlong2 dv = p2[(E + e) >> 1];                       // E even
        s0 = (int)sv.x; s1 = (int)sv.y;
        d0 = (int)dv.x; d1 = (int)dv.y;
    } else {
        const int2* p2 = (const int2*)ei;
        int2 sv = p2[e >> 1];
        int2 dv = p2[(E + e) >> 1];
        s0 = sv.x; s1 = sv.y;
        d0 = dv.x; d1 = dv.y;
    }
    ((int2*)g_src)[e >> 1] = make_int2(s0, s1);
    ((int2*)g_dst)[e >> 1] = make_int2(d0, d1);
    int r0 = atomicAdd(&g_deg[d0], 1);
    int r1 = two ? atomicAdd(&g_deg[d1], 1) : 0;
    ((int2*)g_rank)[e >> 1] = make_int2(r0, r1);
}

// ================= CSR kernels B-D: 3-phase scan (no grid barrier) =========
__global__ void __launch_bounds__(1024) k_scan1(int N) {
    __shared__ int wsum[32];
    int t = threadIdx.x;
    int i = blockIdx.x * 1024 + t;
    int lane = t & 31, wid = t >> 5;
    int v = (i < N) ? g_deg[i] : 0;
    int sc = v;
#pragma unroll
    for (int o = 1; o < 32; o <<= 1) {
        int u = __shfl_up_sync(0xffffffffu, sc, o);
        if (lane >= o) sc += u;
    }
    if (lane == 31) wsum[wid] = sc;
    __syncthreads();
    if (wid == 0) {
        int wv = wsum[lane];
        int ws = wv;
#pragma unroll
        for (int o = 1; o < 32; o <<= 1) {
            int u = __shfl_up_sync(0xffffffffu, ws, o);
            if (lane >= o) ws += u;
        }
        wsum[lane] = ws - wv;   // exclusive warp offsets
    }
    __syncthreads();
    if (i < N) g_incl[i] = sc + wsum[wid];
    if (t == 1023) g_bsum[blockIdx.x] = sc + wsum[wid];
}

__global__ void k_scan2(int nblk) {
    __shared__ int wsum[32];
    int t = threadIdx.x;
    int lane = t & 31, wid = t >> 5;
    int v = (t < nblk) ? g_bsum[t] : 0;
    int sc = v;
#pragma unroll
    for (int o = 1; o < 32; o <<= 1) {
        int u = __shfl_up_sync(0xffffffffu, sc, o);
        if (lane >= o) sc += u;
    }
    if (lane == 31) wsum[wid] = sc;
    __syncthreads();
    if (wid == 0) {
        int wv = wsum[lane];
        int ws = wv;
#pragma unroll
        for (int o = 1; o < 32; o <<= 1) {
            int u = __shfl_up_sync(0xffffffffu, ws, o);
            if (lane >= o) ws += u;
        }
        wsum[lane] = ws - wv;
    }
    __syncthreads();
    if (t < 256) g_boff[t] = sc + wsum[wid] - v;   // exclusive
}

__global__ void k_scan3(int N) {
    int i = blockIdx.x * blockDim.x + threadIdx.x;
    if (i >= N) return;
    int v = g_deg[i];
    int tot = g_incl[i] + g_boff[i >> 10];
    g_rs[i] = tot - v;
    g_re[i] = tot;
    g_deg[i] = 0;                      // restore for next replay
}

// ================= CSR kernel E: scatter (atomic-free) =====================
__global__ void k_scatter(int E) {
    int e = blockIdx.x * blockDim.x + threadIdx.x;
    if (e >= E) return;
    int pos = g_rs[g_dst[e]] + g_rank[e];
    g_csr[pos] = g_src[e];
}

// ================= main-stream kernel: MLP (f32x2, 5 CTAs/SM) ==============
// Register-capped redesign: only a 16KB weight chunk resident at a time.
//   [WREG 16K]: W1 k-half0 -> W1 k-half1 -> W2 (reloaded behind barriers)
//   [XT 17.4K]: xs_t chunk -> ht_t -> stage (phase-overlaid)
// smem 34304 B; __launch_bounds__(256,5) caps regs at 51 -> 40 warps/SM.
#define WREG_OFF  0            // 16384 B (float2[64*32])
#define BIAS_OFF  16384        // 512 B
#define XT_OFF    16896        // 64 x 68 floats = 17408 -> ends 34304
#define HT_OFF    16896
#define STG_OFF   16896        // stage: 64 x 64 floats = 16384 (overlays ht_t)
#define SMEM_SZ   34304

__global__ void __launch_bounds__(256, 5) k_mlp(
    const float* __restrict__ x, const float* __restrict__ b1,
    const float* __restrict__ b2, const float* __restrict__ W1,
    const float* __restrict__ W2, int N)
{
    extern __shared__ char sm[];
    float2* Wreg = (float2*)(sm + WREG_OFF);
    float* bias = (float*)(sm + BIAS_OFF);
    float* xs_t = (float*)(sm + XT_OFF);
    float* ht_t = (float*)(sm + HT_OFF);
    float* stage = (float*)(sm + STG_OFF);

    int tid = threadIdx.x;
    int wid = tid >> 5, lane = tid & 31;
    int node0 = blockIdx.x * 64;
    int w8 = wid * 8;

    if (tid < 64) { bias[tid] = b1[tid]; bias[64 + tid] = b2[tid]; }

    // ---- GEMM1: two k-halves; W1 chunk + x chunk loaded per half ----
    ull acc0[4], acc1[4];
#pragma unroll
    for (int p = 0; p < 4; p++) { acc0[p] = 0ull; acc1[p] = 0ull; }

#pragma unroll
    for (int half = 0; half < 2; half++) {
        // W1 chunk interleaved: Wreg[i*32+l] = (W1[h*64+i][l], W1[h*64+i][l+32])
        for (int idx = tid; idx < 64 * 32; idx += 256) {
            int i = idx >> 5, l = idx & 31;
            Wreg[idx] = make_float2(W1[(half * 64 + i) * 64 + l],
                                    W1[(half * 64 + i) * 64 + l + 32]);
        }
        // x chunk transposed
        for (int idx = tid; idx < 64 * 64; idx += 256) {
            int n = idx >> 6, i = idx & 63;
            int node = node0 + n;
            float v = (node < N) ? x[(size_t)node * 128 + half * 64 + i] : 0.f;
            xs_t[i * 68 + n] = v;
        }
        __syncthreads();
#pragma unroll 2
        for (int i = 0; i < 64; i++) {
            float2 w = Wreg[i * 32 + lane];
            ull wp0 = pack2(w.x, w.x);
            ull wp1 = pack2(w.y, w.y);
            ulonglong2 a01 = *(const ulonglong2*)(xs_t + i * 68 + w8);
            ulonglong2 a23 = *(const ulonglong2*)(xs_t + i * 68 + w8 + 4);
            ffma2(acc0[0], a01.x, wp0); ffma2(acc1[0], a01.x, wp1);
            ffma2(acc0[1], a01.y, wp0); ffma2(acc1[1], a01.y, wp1);
            ffma2(acc0[2], a23.x, wp0); ffma2(acc1[2], a23.x, wp1);
            ffma2(acc0[3], a23.y, wp0); ffma2(acc1[3], a23.y, wp1);
        }
        __syncthreads();   // Wreg + xs_t dead for this half
    }

    // load W2 interleaved into WREG (same 16K region)
    for (int idx = tid; idx < 64 * 32; idx += 256) {
        int i = idx >> 5, l = idx & 31;
        Wreg[idx] = make_float2(W2[i * 64 + l], W2[i * 64 + l + 32]);
    }

    // epilogue1: relu(+b1) -> ht_t[c*68 + n] (overlays dead xs_t)
    {
        float bA = bias[lane], bB = bias[lane + 32];
#pragma unroll
        for (int p = 0; p < 4; p++) {
            float hx, hy;
            unpack2(acc0[p], hx, hy);
            ht_t[lane * 68 + w8 + 2 * p]     = fmaxf(hx + bA, 0.f);
            ht_t[lane * 68 + w8 + 2 * p + 1] = fmaxf(hy + bA, 0.f);
            unpack2(acc1[p], hx, hy);
            ht_t[(lane + 32) * 68 + w8 + 2 * p]     = fmaxf(hx + bB, 0.f);
            ht_t[(lane + 32) * 68 + w8 + 2 * p + 1] = fmaxf(hy + bB, 0.f);
        }
    }
    __syncthreads();

    // ---- GEMM2 ----
#pragma unroll
    for (int p = 0; p < 4; p++) { acc0[p] = 0ull; acc1[p] = 0ull; }
#pragma unroll 2
    for (int i = 0; i < 64; i++) {
        float2 w = Wreg[i * 32 + lane];
        ull wp0 = pack2(w.x, w.x);
        ull wp1 = pack2(w.y, w.y);
        ulonglong2 a01 = *(const ulonglong2*)(ht_t + i * 68 + w8);
        ulonglong2 a23 = *(const ulonglong2*)(ht_t + i * 68 + w8 + 4);
        ffma2(acc0[0], a01.x, wp0); ffma2(acc1[0], a01.x, wp1);
        ffma2(acc0[1], a01.y, wp0); ffma2(acc1[1], a01.y, wp1);
        ffma2(acc0[2], a23.x, wp0); ffma2(acc1[2], a23.x, wp1);
        ffma2(acc0[3], a23.y, wp0); ffma2(acc1[3], a23.y, wp1);
    }
    __syncthreads();   // all ht_t reads done before stage overlays it

    // epilogue2: +b2 -> stage[n*64 + c] (overlays dead ht_t)
    {
        float bA = bias[64 + lane], bB = bias[64 + lane + 32];
#pragma unroll
        for (int p = 0; p < 4; p++) {
            float hx, hy;
            unpack2(acc0[p], hx, hy);
            stage[(w8 + 2 * p) * 64 + lane]     = hx + bA;
            stage[(w8 + 2 * p + 1) * 64 + lane] = hy + bA;
            unpack2(acc1[p], hx, hy);
            stage[(w8 + 2 * p) * 64 + lane + 32]     = hx + bB;
            stage[(w8 + 2 * p + 1) * 64 + lane + 32] = hy + bB;
        }
    }
    __syncthreads();

    // norms + coalesced global store
    {
        float2* gh2 = (float2*)g_h;
        const float2* st2 = (const float2*)stage;
#pragma unroll
        for (int r = 0; r < 8; r++) {
            int n = w8 + r;
            int node = node0 + n;
            float2 v = st2[n * 32 + lane];
            float ss = v.x * v.x + v.y * v.y;
#pragma unroll
            for (int o = 16; o; o >>= 1) ss += __shfl_xor_sync(0xffffffffu, ss, o);
            if (node < N) {
                gh2[(size_t)node * 32 + lane] = v;
                if (lane == 0) g_rnorm[node] = 1.f / fmaxf(sqrtf(ss), 1e-12f);
            }
        }
    }
}

// ================= final kernel: gather (octet-per-edge, R15/fp32 exact) ===
__global__ void __launch_bounds__(256, 4) k_gather(
    const float* __restrict__ beta_p, const float* __restrict__ Wc,
    const float* __restrict__ bc, float* __restrict__ out, int N)
{
    int wid = threadIdx.x >> 5;
    int lane = threadIdx.x & 31;
    int p8 = lane & 7, oc = lane >> 3;
    int n = blockIdx.x * 8 + wid;
    if (n >= N) return;

    float beta = __ldg(beta_p);
    float C = fabsf(beta);                 // |e| <= |beta| -> fixed softmax shift
    const ulonglong2* h16 = (const ulonglong2*)g_h;

    size_t rowd = (size_t)n * 16;
    ulonglong2 hd0 = h16[rowd + p8];
    ulonglong2 hd1 = h16[rowd + 8 + p8];
    float rnd = __ldg(&g_rnorm[n]);

    ull d2 = 0ull;
    ffma2(d2, hd0.x, hd0.x); ffma2(d2, hd0.y, hd0.y);
    ffma2(d2, hd1.x, hd1.x); ffma2(d2, hd1.y, hd1.y);
    float dsx, dsy; unpack2(d2, dsx, dsy);
    float ds = dsx + dsy;
    ds += __shfl_xor_sync(0xffffffffu, ds, 1);
    ds += __shfl_xor_sync(0xffffffffu, ds, 2);
    ds += __shfl_xor_sync(0xffffffffu, ds, 4);
    float w_self = __expf(fmaf(beta * rnd * rnd, ds, -C));

    float wq = (oc == 0) ? w_self : 0.f;
    ull wqp = pack2(wq, wq);
    ull acc[4];
    acc[0] = 0ull; acc[1] = 0ull; acc[2] = 0ull; acc[3] = 0ull;
    ffma2(acc[0], wqp, hd0.x); ffma2(acc[1], wqp, hd0.y);
    ffma2(acc[2], wqp, hd1.x); ffma2(acc[3], wqp, hd1.y);
    float s_lane = 0.f;

    int start = g_rs[n], end = g_re[n];
    float brnd = beta * rnd;
    for (int e0 = start; e0 < end; e0 += 4) {
        int eidx = e0 + oc;
        bool valid = eidx < end;
        int sidx = __ldg(&g_csr[valid ? eidx : e0]);
        float rns = __ldg(&g_rnorm[sidx]);
        size_t srow = (size_t)sidx * 16;
        ulonglong2 hs0 = h16[srow + p8];
        ulonglong2 hs1 = h16[srow + 8 + p8];

        ull dd = 0ull;
        ffma2(dd, hs0.x, hd0.x); ffma2(dd, hs0.y, hd0.y);
        ffma2(dd, hs1.x, hd1.x); ffma2(dd, hs1.y, hd1.y);
        float dx, dy; unpack2(dd, dx, dy);
        float d = dx + dy;
        d += __shfl_xor_sync(0xffffffffu, d, 1);
        d += __shfl_xor_sync(0xffffffffu, d, 2);
        d += __shfl_xor_sync(0xffffffffu, d, 4);

        float w = __expf(fmaf(brnd * rns, d, -C));
        w = valid ? w : 0.f;
        s_lane += w;
        ull wp = pack2(w, w);
        ffma2(acc[0], wp, hs0.x); ffma2(acc[1], wp, hs0.y);
        ffma2(acc[2], wp, hs1.x); ffma2(acc[3], wp, hs1.y);
    }

#pragma unroll
    for (int o = 16; o; o >>= 1) s_lane += __shfl_xor_sync(0xffffffffu, s_lane, o);
    float s = fmaf(s_lane, 0.125f, w_self);
    float inv = 1.f / (s + 1e-16f);

    const float2* wc2 = (const float2*)Wc;
    float y0 = 0.f, y1 = 0.f;
    {
        int c0 = 4 * p8;
        float a0, a1, a2, a3;
        unpack2(acc[0], a0, a1);
        unpack2(acc[1], a2, a3);
        float2 w0 = wc2[c0], w1 = wc2[c0 + 1], w2 = wc2[c0 + 2], w3 = wc2[c0 + 3];
        y0 += a0 * w0.x + a1 * w1.x + a2 * w2.x + a3 * w3.x;
        y1 += a0 * w0.y + a1 * w1.y + a2 * w2.y + a3 * w3.y;
        int c1 = 32 + 4 * p8;
        unpack2(acc[2], a0, a1);
        unpack2(acc[3], a2, a3);
        w0 = wc2[c1]; w1 = wc2[c1 + 1]; w2 = wc2[c1 + 2]; w3 = wc2[c1 + 3];
        y0 += a0 * w0.x + a1 * w1.x + a2 * w2.x + a3 * w3.x;
        y1 += a0 * w0.y + a1 * w1.y + a2 * w2.y + a3 * w3.y;
    }
#pragma unroll
    for (int o = 16; o; o >>= 1) {
        y0 += __shfl_xor_sync(0xffffffffu, y0, o);
        y1 += __shfl_xor_sync(0xffffffffu, y1, o);
    }
    if (lane == 0) {
        out[(size_t)n * 2]     = fmaf(y0, inv, __ldg(&bc[0]));
        out[(size_t)n * 2 + 1] = fmaf(y1, inv, __ldg(&bc[1]));
    }
}

// ---------------- launch: forked-stream graph ------------------------------
extern "C" void kernel_launch(void* const* d_in, const int* in_sizes, int n_in,
                              void* d_out, int out_size)
{
    const float* x    = (const float*)d_in[0];
    const void*  ei   = d_in[1];
    const float* W1   = (const float*)d_in[2];
    const float* b1   = (const float*)d_in[3];
    const float* W2   = (const float*)d_in[4];
    const float* b2   = (const float*)d_in[5];
    const float* beta = (const float*)d_in[6];
    const float* Wc   = (const float*)d_in[7];
    const float* bc   = (const float*)d_in[8];
    float* y = (float*)d_out;

    int hid    = in_sizes[3];            // 64
    int in_dim = in_sizes[2] / hid;      // 128
    int N      = in_sizes[0] / in_dim;   // 100000
    int E      = in_sizes[1] / 2;        // 1600000

    static cudaStream_t s2 = nullptr;
    static cudaEvent_t evFork = nullptr, evJoin = nullptr;
    if (s2 == nullptr) {
        cudaStreamCreateWithFlags(&s2, cudaStreamNonBlocking);
        cudaEventCreateWithFlags(&evFork, cudaEventDisableTiming);
        cudaEventCreateWithFlags(&evJoin, cudaEventDisableTiming);
        cudaFuncSetAttribute(k_mlp, cudaFuncAttributeMaxDynamicSharedMemorySize, SMEM_SZ);
    }

    int nblk = (N + 1023) / 1024;        // 98 blocks

    // fork: side stream begins after everything previously on main stream
    cudaEventRecord(evFork, 0);
    cudaStreamWaitEvent(s2, evFork, 0);

    k_convcount<<<(E / 2 + 255) / 256, 256, 0, s2>>>(ei, E, N);     // 1 (s2)
    k_scan1<<<nblk, 1024, 0, s2>>>(N);                              // 2 (s2)
    k_scan2<<<1, 256, 0, s2>>>(nblk);                               // 3 (s2)
    k_mlp<<<(N + 63) / 64, 256, SMEM_SZ>>>(x, b1, b2, W1, W2, N);   // 4 (main, profiled)
    k_scan3<<<(N + 255) / 256, 256, 0, s2>>>(N);                    // 5 (s2)
    k_scatter<<<(E + 255) / 256, 256, 0, s2>>>(E);                  // 6 (s2)

    // join: gather needs both the CSR (s2) and h/rnorm (main)
    cudaEventRecord(evJoin, s2);
    cudaStreamWaitEvent(0, evJoin, 0);
    k_gather<<<(N + 7) / 8, 256>>>(beta, Wc, bc, y, N);             // 7 (main)
}